// round 7
// baseline (speedup 1.0000x reference)
#include <cuda_runtime.h>
#include <cuda_fp16.h>

#define NAB 10
#define MAXN 131072
#define CHUNK 4

static __device__ int g_cnt[NAB];
static __device__ int g_off[NAB+1];
static __device__ int g_cursor[NAB];
static __device__ int g_tb_s[NAB+1];
static __device__ int g_tb_v[NAB+1];
static __device__ int g_zn[MAXN];
static __device__ int g_perm[MAXN];
static __device__ int g_work;
// fp16 weights: [20 mats][4 k-chunks][128 o][72 k-pad] (144B rows; pad stays 0)
static __device__ __half g_Wh[20*4*128*72];

__device__ __forceinline__ unsigned su32(const void* p){
  return (unsigned)__cvta_generic_to_shared(p);
}
__device__ __forceinline__ void ldsm4(unsigned r[4], unsigned addr){
  asm volatile("ldmatrix.sync.aligned.m8n8.x4.shared.b16 {%0,%1,%2,%3}, [%4];"
    : "=r"(r[0]),"=r"(r[1]),"=r"(r[2]),"=r"(r[3]) : "r"(addr));
}
__device__ __forceinline__ void hmma(float c[4], const unsigned a[4],
                                     unsigned b0, unsigned b1){
  asm volatile("mma.sync.aligned.m16n8k16.row.col.f32.f16.f16.f32 "
    "{%0,%1,%2,%3},{%4,%5,%6,%7},{%8,%9},{%0,%1,%2,%3};"
    : "+f"(c[0]),"+f"(c[1]),"+f"(c[2]),"+f"(c[3])
    : "r"(a[0]),"r"(a[1]),"r"(a[2]),"r"(a[3]),"r"(b0),"r"(b1));
}

// ---------- setup kernels ----------
__global__ void k_prepw(const float* __restrict__ Wl0, const float* __restrict__ Wl1,
                        const float* __restrict__ Wt0, const float* __restrict__ Wt1){
  int idx = blockIdx.x*blockDim.x + threadIdx.x;
  if (idx >= 20*32768) return;
  int mat = idx >> 15;
  int r = idx & 32767;
  int k = r >> 7, o = r & 127;
  int type = mat / 10, a = mat - type*10;
  float v;
  if (k < 128) {
    const float* W = type ? Wl1 : Wl0;
    v = W[k*128 + o] * 0.08838834764831845f;                 // LIN: 1/sqrt(128)
  } else {
    const float* W = type ? Wt1 : Wt0;
    v = W[(k-128)*1280 + a*128 + o] * 0.027950849718747373f; // TP: 1/sqrt(1280)
  }
  int kc = k >> 6, kk = k & 63;
  g_Wh[(size_t)mat*36864 + kc*9216 + o*72 + kk] = __float2half_rn(v);
}

__global__ void k_zero(){ if (threadIdx.x < NAB) g_cnt[threadIdx.x] = 0; }

__global__ void k_hist(const float* __restrict__ attrs, int N){
  __shared__ int s[NAB];
  if (threadIdx.x < NAB) s[threadIdx.x] = 0;
  __syncthreads();
  int n = blockIdx.x*blockDim.x + threadIdx.x;
  if (n < N){
    const float* p = attrs + (size_t)n*NAB;
    int a = 0; float best = p[0];
    #pragma unroll
    for (int i=1;i<NAB;++i){ float v=p[i]; if (v>best){best=v;a=i;} }
    g_zn[n] = a;
    atomicAdd(&s[a], 1);
  }
  __syncthreads();
  if (threadIdx.x < NAB) atomicAdd(&g_cnt[threadIdx.x], s[threadIdx.x]);
}

__global__ void k_scan(){
  if (threadIdx.x == 0 && blockIdx.x == 0){
    g_work = 0;
    g_off[0]=0; g_tb_s[0]=0; g_tb_v[0]=0;
    for (int a=0;a<NAB;++a){
      int c = g_cnt[a];
      g_off[a+1]  = g_off[a] + c;
      g_cursor[a] = g_off[a];
      g_tb_s[a+1] = g_tb_s[a] + (c + 63)/64;
      g_tb_v[a+1] = g_tb_v[a] + (c + 20)/21;
    }
  }
}

__global__ void k_scatter(int N){
  __shared__ int sc[NAB], sb[NAB];
  if (threadIdx.x < NAB) sc[threadIdx.x] = 0;
  __syncthreads();
  int n = blockIdx.x*blockDim.x + threadIdx.x;
  int a = 0, p = 0;
  bool valid = (n < N);
  if (valid){ a = g_zn[n]; p = atomicAdd(&sc[a], 1); }
  __syncthreads();
  if (threadIdx.x < NAB) sb[threadIdx.x] = atomicAdd(&g_cursor[threadIdx.x], sc[threadIdx.x]);
  __syncthreads();
  if (valid) g_perm[sb[a] + p] = n;
}

// ---------- main kernel helpers ----------
__device__ __forceinline__ void meta(int t, int ts_tot,
    int& isv, int& base, int& end, int& key, int& width){
  isv = (t >= ts_tot) ? 1 : 0;
  int tt = isv ? t - ts_tot : t;
  const int* tb = isv ? g_tb_v : g_tb_s;
  int a = 0;
  while (tt >= tb[a+1]) ++a;
  int tile = tt - tb[a];
  width = isv ? 21 : 64;
  base = g_off[a] + tile*width;
  end  = g_off[a+1];
  key  = (isv ? NAB : 0) + a;
}

// 256 threads; s: 1024 float4 (64 rows x 16), v: 1008 float4 (21 nodes x 48)
__device__ __forceinline__ void pf_ld(const float* __restrict__ src, int cb, int isv,
                                      const int* sn, int tid, float4 pv[4]){
  if (!isv){
    #pragma unroll
    for (int i=0;i<4;++i){
      int q = tid + i*256;
      int ln = q>>4, u=(q&15)<<2;
      int node = sn[ln];
      if (node>=0) pv[i] = *(const float4*)(src + (size_t)node*512 + cb + u);
    }
  } else {
    #pragma unroll
    for (int i=0;i<4;++i){
      int q = tid + i*256;
      if (q>=1008) break;
      int ln = q/48, u=(q-ln*48)<<2;
      int node = sn[ln];
      if (node>=0) pv[i] = *(const float4*)(src + (size_t)node*512 + cb + u);
    }
  }
}
__device__ __forceinline__ void pf_st(char* Ad, int isv, const int* sn, int tid,
                                      const float4 pv[4]){
  if (!isv){
    #pragma unroll
    for (int i=0;i<4;++i){
      int q = tid + i*256;
      int ln = q>>4, u=(q&15)<<2;
      if (sn[ln] < 0) continue;
      __half2* d = (__half2*)(Ad + ln*144 + u*2);
      d[0] = __floats2half2_rn(pv[i].x, pv[i].y);
      d[1] = __floats2half2_rn(pv[i].z, pv[i].w);
    }
  } else {
    #pragma unroll
    for (int i=0;i<4;++i){
      int q = tid + i*256;
      if (q>=1008) break;
      int ln = q/48, u=(q-ln*48)<<2;
      if (sn[ln] < 0) continue;
      float vv[4] = {pv[i].x, pv[i].y, pv[i].z, pv[i].w};
      #pragma unroll
      for (int e=0;e<4;++e){
        int jr = u + e;
        int il = jr/3, x = jr - 3*il;
        *(__half*)(Ad + (3*ln + x)*144 + il*2) = __float2half_rn(vv[e]);
      }
    }
  }
}

// ---------- main kernel ----------
// SMEM: [0, 73728)           B weights: 4 chunks x [128 o][72 halves] (144B rows)
//       [73728, 73728+18432) A double buffer: 2 x [64 m][72 halves]
//       epilogue reuses A region as stage [64][68] fp32 (17408B)
#define B_BYTES   73728
#define A_BYTES   9216
#define SMEM_BYTES (B_BYTES + 2*A_BYTES)

__global__ void __launch_bounds__(256) k_main(
    const float* __restrict__ Xm, const float* __restrict__ Xf,
    float* __restrict__ out){
  extern __shared__ char smem[];
  char*  Abuf  = smem + B_BYTES;
  float* stage = (float*)(smem + B_BYTES);
  __shared__ int snode[2][64];
  __shared__ int s_grab;

  const int tid  = threadIdx.x;
  const int lane = tid & 31;
  const int wid  = tid >> 5;
  const int wm = wid & 1, wn = wid >> 1;   // 2x4 warps, each 32 rows x 32 cols
  const int g4 = lane >> 2, t4 = lane & 3;
  const unsigned smb = su32(smem);
  const unsigned Ab  = smb + B_BYTES;

  const int ra  = lane & 15;
  const int ca  = (lane >> 4) << 3;
  const int rb  = ((lane >> 4) & 1)*8 + (lane & 7);
  const int cb2 = ((lane >> 3) & 1) << 3;

  const int ts_tot = g_tb_s[NAB];
  const int tv_tot = g_tb_v[NAB];
  const int total  = ts_tot + tv_tot;

  if (tid == 0) s_grab = atomicAdd(&g_work, CHUNK);
  __syncthreads();
  int rs = s_grab;
  int re = rs + CHUNK; if (re > total) re = total;
  int t = rs;
  int cur = -1, sp = 0;
  bool havePre = false;
  float4 pv[4];   // prefetched next-tile chunk0 (held across epilogue)

  while (t < total){
    int isv, base, end, key, width;
    meta(t, ts_tot, isv, base, end, key, width);
    if (t == re-1 && tid == 0) s_grab = atomicAdd(&g_work, CHUNK);
    if (!havePre && tid < width)
      snode[sp][tid] = (base + tid < end) ? g_perm[base + tid] : -1;
    if (key != cur){
      cur = key;
      const float4* srcW = (const float4*)(g_Wh + (size_t)key*36864);
      float4* dstW = (float4*)smem;
      #pragma unroll 6
      for (int q = tid; q < 4608; q += 256) dstW[q] = srcW[q];
    }
    __syncthreads();   // B0: B, snode, s_grab visible; prev tile stage reads done

    if (havePre){
      pf_st(Abuf, isv, snode[sp], tid, pv);       // STS prefetched chunk0 -> buf0
    } else {
      pf_ld(Xm, isv ? 128 : 0, isv, snode[sp], tid, pv);
      pf_st(Abuf, isv, snode[sp], tid, pv);
    }
    __syncthreads();   // B1: buf0 visible

    int nt = (t+1 < re) ? t+1 : s_grab;
    const bool hasN = (nt < total);
    int nisv=0, nbase=0, nend=0, nkey=0, nwidth=0;
    if (hasN) meta(nt, ts_tot, nisv, nbase, nend, nkey, nwidth);

    float acc[2][4][4];
    #pragma unroll
    for (int i=0;i<2;++i)
      #pragma unroll
      for (int j=0;j<4;++j)
        #pragma unroll
        for (int e=0;e<4;++e) acc[i][j][e] = 0.f;

    for (int kc = 0; kc < 4; ++kc){
      if (kc > 0) __syncthreads();   // STS of chunk kc visible; buf (kc+1)&1 free

      // ---- prefetch chunk kc+1 of this tile ----
      float4 qv[4];
      if (kc < 3){
        int nk = kc + 1;
        const float* psrc = (nk < 2) ? Xm : Xf;
        int pcb = isv ? 128 + (nk & 1)*192 : (nk & 1)*64;
        pf_ld(psrc, pcb, isv, snode[sp], tid, qv);
      }
      if (kc == 2 && hasN && tid < nwidth)
        snode[sp^1][tid] = (nbase + tid < nend) ? g_perm[nbase + tid] : -1;

      // ---- MMA on chunk kc ----
      const unsigned Ac = Ab + (unsigned)((kc & 1)*A_BYTES);
      const unsigned Bk = smb + (unsigned)(kc*18432);
      #pragma unroll
      for (int ks = 0; ks < 4; ++ks){
        const int k0 = ks*16;
        unsigned af[2][4], bf[2][4];
        ldsm4(af[0], Ac + (unsigned)((wm*32      + ra)*144 + (k0+ca)*2));
        ldsm4(af[1], Ac + (unsigned)((wm*32 + 16 + ra)*144 + (k0+ca)*2));
        ldsm4(bf[0], Bk + (unsigned)((wn*32      + rb)*144 + (k0+cb2)*2));
        ldsm4(bf[1], Bk + (unsigned)((wn*32 + 16 + rb)*144 + (k0+cb2)*2));
        #pragma unroll
        for (int mi = 0; mi < 2; ++mi){
          hmma(acc[mi][0], af[mi], bf[0][0], bf[0][1]);
          hmma(acc[mi][1], af[mi], bf[0][2], bf[0][3]);
          hmma(acc[mi][2], af[mi], bf[1][0], bf[1][1]);
          hmma(acc[mi][3], af[mi], bf[1][2], bf[1][3]);
        }
      }

      if (kc < 3)
        pf_st(Abuf + ((kc+1) & 1)*A_BYTES, isv, snode[sp], tid, qv);
    }
    __syncthreads();  // B5: all MMAs done; A region (stage) free; snode[sp^1] visible

    // ---- prefetch next tile's chunk0 (LDG only; STS after next B0) ----
    if (hasN) pf_ld(Xm, nisv ? 128 : 0, nisv, snode[sp^1], tid, pv);

    // ---- epilogue: two 64-col passes through stage (= A region) ----
    #pragma unroll
    for (int p = 0; p < 2; ++p){
      if (p) __syncthreads();        // stage reads of pass0 done
      if ((wn >> 1) == p){
        int lcb = (wn & 1)*32;
        #pragma unroll
        for (int mi = 0; mi < 2; ++mi){
          int r = wm*32 + mi*16 + g4;
          #pragma unroll
          for (int jj = 0; jj < 4; ++jj){
            int c = lcb + jj*8 + 2*t4;
            float* d1 = stage + r*68 + c;
            d1[0] = acc[mi][jj][0]; d1[1] = acc[mi][jj][1];
            float* d2 = stage + (r+8)*68 + c;
            d2[0] = acc[mi][jj][2]; d2[1] = acc[mi][jj][3];
          }
        }
      }
      __syncthreads();               // stage pass p ready
      if (!isv){
        #pragma unroll
        for (int i = 0; i < 4; ++i){
          int q = tid + i*256;
          int ln = q >> 4, u = (q & 15) << 2;
          int node = snode[sp][ln];
          if (node < 0) continue;
          float4 v = *(float4*)(stage + ln*68 + u);
          *(float4*)(out + (size_t)node*512 + p*64 + u) = v;
        }
      } else {
        #pragma unroll
        for (int i = 0; i < 4; ++i){
          int q = tid + i*256;
          if (q >= 1008) break;
          int ln = q / 48, u = (q - ln*48) << 2;
          int node = snode[sp][ln];
          if (node < 0) continue;
          float4 v;
          float* vp = (float*)&v;
          #pragma unroll
          for (int e=0;e<4;++e){
            int jr = u + e;
            int ol = jr/3, x = jr - 3*ol;
            vp[e] = stage[(3*ln + x)*68 + ol];
          }
          *(float4*)(out + (size_t)node*512 + 128 + p*192 + u) = v;
        }
      }
    }

    // ---- advance (B0 of next iteration guards stage reuse) ----
    havePre = hasN;
    sp ^= 1;
    if (t+1 < re){ t = t+1; }
    else { rs = nt; re = rs + CHUNK; if (re > total) re = total; t = nt; }
  }
}

extern "C" void kernel_launch(void* const* d_in, const int* in_sizes, int n_in,
                              void* d_out, int out_size){
  const float* m_i   = (const float*)d_in[0];
  const float* nfeat = (const float*)d_in[1];
  const float* attrs = (const float*)d_in[2];
  const float* Wl0   = (const float*)d_in[3];
  const float* Wl1   = (const float*)d_in[4];
  const float* Wt0   = (const float*)d_in[5];
  const float* Wt1   = (const float*)d_in[6];
  float* out = (float*)d_out;
  int N = in_sizes[0] / 512;
  if (N > MAXN) return;

  cudaFuncSetAttribute(k_main, cudaFuncAttributeMaxDynamicSharedMemorySize, SMEM_BYTES);

  k_prepw<<<(20*32768 + 255)/256, 256>>>(Wl0, Wl1, Wt0, Wt1);
  k_zero<<<1, 32>>>();
  k_hist<<<(N + 255)/256, 256>>>(attrs, N);
  k_scan<<<1, 1>>>();
  k_scatter<<<(N + 255)/256, 256>>>(N);
  k_main<<<296, 256, SMEM_BYTES>>>(m_i, nfeat, out);
}

// round 8
// speedup vs baseline: 1.1998x; 1.1998x over previous
#include <cuda_runtime.h>
#include <cuda_fp16.h>

#define NAB 10
#define MAXN 131072
#define CHUNK 4

static __device__ int g_cnt[NAB];
static __device__ int g_off[NAB+1];
static __device__ int g_cursor[NAB];
static __device__ int g_tb_s[NAB+1];
static __device__ int g_tb_v[NAB+1];
static __device__ int g_zn[MAXN];
static __device__ int g_perm[MAXN];
static __device__ int g_work;
// fp16 weights: [20 mats][4 k-chunks][128 o][72 k-pad] (144B rows; pad stays 0)
static __device__ __half g_Wh[20*4*128*72];

__device__ __forceinline__ unsigned su32(const void* p){
  return (unsigned)__cvta_generic_to_shared(p);
}
__device__ __forceinline__ void ldsm4(unsigned r[4], unsigned addr){
  asm volatile("ldmatrix.sync.aligned.m8n8.x4.shared.b16 {%0,%1,%2,%3}, [%4];"
    : "=r"(r[0]),"=r"(r[1]),"=r"(r[2]),"=r"(r[3]) : "r"(addr));
}
__device__ __forceinline__ void hmma(float c[4], const unsigned a[4],
                                     unsigned b0, unsigned b1){
  asm volatile("mma.sync.aligned.m16n8k16.row.col.f32.f16.f16.f32 "
    "{%0,%1,%2,%3},{%4,%5,%6,%7},{%8,%9},{%0,%1,%2,%3};"
    : "+f"(c[0]),"+f"(c[1]),"+f"(c[2]),"+f"(c[3])
    : "r"(a[0]),"r"(a[1]),"r"(a[2]),"r"(a[3]),"r"(b0),"r"(b1));
}

// ---------- setup kernels ----------
__global__ void k_prepw(const float* __restrict__ Wl0, const float* __restrict__ Wl1,
                        const float* __restrict__ Wt0, const float* __restrict__ Wt1){
  int idx = blockIdx.x*blockDim.x + threadIdx.x;
  if (idx >= 20*32768) return;
  int mat = idx >> 15;
  int r = idx & 32767;
  int k = r >> 7, o = r & 127;
  int type = mat / 10, a = mat - type*10;
  float v;
  if (k < 128) {
    const float* W = type ? Wl1 : Wl0;
    v = W[k*128 + o] * 0.08838834764831845f;                 // LIN: 1/sqrt(128)
  } else {
    const float* W = type ? Wt1 : Wt0;
    v = W[(k-128)*1280 + a*128 + o] * 0.027950849718747373f; // TP: 1/sqrt(1280)
  }
  int kc = k >> 6, kk = k & 63;
  g_Wh[(size_t)mat*36864 + kc*9216 + o*72 + kk] = __float2half_rn(v);
}

__global__ void k_zero(){ if (threadIdx.x < NAB) g_cnt[threadIdx.x] = 0; }

__global__ void k_hist(const float* __restrict__ attrs, int N){
  __shared__ int s[NAB];
  if (threadIdx.x < NAB) s[threadIdx.x] = 0;
  __syncthreads();
  int n = blockIdx.x*blockDim.x + threadIdx.x;
  if (n < N){
    const float* p = attrs + (size_t)n*NAB;
    int a = 0; float best = p[0];
    #pragma unroll
    for (int i=1;i<NAB;++i){ float v=p[i]; if (v>best){best=v;a=i;} }
    g_zn[n] = a;
    atomicAdd(&s[a], 1);
  }
  __syncthreads();
  if (threadIdx.x < NAB) atomicAdd(&g_cnt[threadIdx.x], s[threadIdx.x]);
}

__global__ void k_scan(){
  if (threadIdx.x == 0 && blockIdx.x == 0){
    g_work = 0;
    g_off[0]=0; g_tb_s[0]=0; g_tb_v[0]=0;
    for (int a=0;a<NAB;++a){
      int c = g_cnt[a];
      g_off[a+1]  = g_off[a] + c;
      g_cursor[a] = g_off[a];
      g_tb_s[a+1] = g_tb_s[a] + (c + 127)/128;
      g_tb_v[a+1] = g_tb_v[a] + (c + 41)/42;
    }
  }
}

__global__ void k_scatter(int N){
  __shared__ int sc[NAB], sb[NAB];
  if (threadIdx.x < NAB) sc[threadIdx.x] = 0;
  __syncthreads();
  int n = blockIdx.x*blockDim.x + threadIdx.x;
  int a = 0, p = 0;
  bool valid = (n < N);
  if (valid){ a = g_zn[n]; p = atomicAdd(&sc[a], 1); }
  __syncthreads();
  if (threadIdx.x < NAB) sb[threadIdx.x] = atomicAdd(&g_cursor[threadIdx.x], sc[threadIdx.x]);
  __syncthreads();
  if (valid) g_perm[sb[a] + p] = n;
}

// ---------- main kernel helpers ----------
struct VTab { int ln[4]; int u[4]; unsigned off[4][4]; };

__device__ __forceinline__ void meta(int t, int ts_tot,
    int& isv, int& base, int& end, int& key, int& width){
  isv = (t >= ts_tot) ? 1 : 0;
  int tt = isv ? t - ts_tot : t;
  const int* tb = isv ? g_tb_v : g_tb_s;
  int a = 0;
  while (tt >= tb[a+1]) ++a;
  int tile = tt - tb[a];
  width = isv ? 42 : 128;
  base = g_off[a] + tile*width;
  end  = g_off[a+1];
  key  = (isv ? NAB : 0) + a;
}

__device__ __forceinline__ void gath_ld(const float* __restrict__ src, int cb, int isv,
                                        const int* sn, int tid, const VTab& vt, float4 pv[4]){
  if (!isv){
    #pragma unroll
    for (int i=0;i<4;++i){
      int q = tid + i*512;
      int ln = q>>4, u=(q&15)<<2;
      int node = sn[ln];
      if (node>=0) pv[i] = *(const float4*)(src + (size_t)node*512 + cb + u);
    }
  } else {
    #pragma unroll
    for (int i=0;i<4;++i){
      if (vt.ln[i] < 0) continue;
      int node = sn[vt.ln[i]];
      if (node>=0) pv[i] = *(const float4*)(src + (size_t)node*512 + cb + vt.u[i]);
    }
  }
}
__device__ __forceinline__ void gath_st(char* Ad, int isv, const int* sn, int tid,
                                        const VTab& vt, const float4 pv[4]){
  if (!isv){
    #pragma unroll
    for (int i=0;i<4;++i){
      int q = tid + i*512;
      int ln = q>>4, u=(q&15)<<2;
      if (sn[ln] < 0) continue;
      __half2* d = (__half2*)(Ad + ln*144 + u*2);
      d[0] = __floats2half2_rn(pv[i].x, pv[i].y);
      d[1] = __floats2half2_rn(pv[i].z, pv[i].w);
    }
  } else {
    #pragma unroll
    for (int i=0;i<4;++i){
      if (vt.ln[i] < 0) continue;
      if (sn[vt.ln[i]] < 0) continue;
      const float vv[4] = {pv[i].x, pv[i].y, pv[i].z, pv[i].w};
      #pragma unroll
      for (int e=0;e<4;++e)
        *(__half*)(Ad + vt.off[i][e]) = __float2half_rn(vv[e]);
    }
  }
}

// ---------- main kernel ----------
// SMEM: [0, 73728)             B weights: 4 chunks x [128 o][72 halves] (144B rows)
//       [73728, 73728+36864)   A double buffer: 2 x [128 m][72 halves]
//       [110592, 110592+67584) C stage [128][132] fp32 (v-tiles only)
#define B_BYTES   73728
#define A_BYTES   18432
#define STAGE_OFF (B_BYTES + 2*A_BYTES)
#define SMEM_BYTES (STAGE_OFF + 128*132*4)

__global__ void __launch_bounds__(512) k_main(
    const float* __restrict__ Xm, const float* __restrict__ Xf,
    float* __restrict__ out){
  extern __shared__ char smem[];
  char*  Abuf  = smem + B_BYTES;
  float* stage = (float*)(smem + STAGE_OFF);
  __shared__ int snode[2][128];
  __shared__ int s_grab;

  const int tid  = threadIdx.x;
  const int lane = tid & 31;
  const int wid  = tid >> 5;
  const int wm = wid & 3, wn = wid >> 2;   // 4x4 warps, each 32 rows x 32 cols
  const int g4 = lane >> 2, t4 = lane & 3;
  const unsigned smb = su32(smem);
  const unsigned Ab  = smb + B_BYTES;

  const int ra  = lane & 15;
  const int ca  = (lane >> 4) << 3;
  const int rb  = ((lane >> 4) & 1)*8 + (lane & 7);
  const int cb2 = ((lane >> 3) & 1) << 3;

  // per-thread v-gather index tables (loop-invariant)
  VTab vt;
  #pragma unroll
  for (int i=0;i<4;++i){
    int q = tid + i*512;
    if (q < 2016){
      int ln = q/48, u = (q - ln*48) << 2;
      vt.ln[i] = ln; vt.u[i] = u;
      #pragma unroll
      for (int e=0;e<4;++e){
        int jr = u + e;
        int il = jr/3, x = jr - 3*il;
        vt.off[i][e] = (unsigned)((3*ln + x)*144 + il*2);
      }
    } else {
      vt.ln[i] = -1; vt.u[i] = 0;
      #pragma unroll
      for (int e=0;e<4;++e) vt.off[i][e] = 0;
    }
  }

  const int ts_tot = g_tb_s[NAB];
  const int tv_tot = g_tb_v[NAB];
  const int total  = ts_tot + tv_tot;

  if (tid == 0) s_grab = atomicAdd(&g_work, CHUNK);
  __syncthreads();
  int rs = s_grab;
  int re = rs + CHUNK; if (re > total) re = total;
  int t = rs;
  int cur = -1, sp = 0;
  bool havePre = false;

  while (t < total){
    int isv, base, end, key, width;
    meta(t, ts_tot, isv, base, end, key, width);
    if (t == re-1 && tid == 0) s_grab = atomicAdd(&g_work, CHUNK);
    if (!havePre && tid < width)
      snode[sp][tid] = (base + tid < end) ? g_perm[base + tid] : -1;
    if (key != cur){
      cur = key;
      const float4* srcW = (const float4*)(g_Wh + (size_t)key*36864);
      float4* dstW = (float4*)smem;
      #pragma unroll 3
      for (int q = tid; q < 4608; q += 512) dstW[q] = srcW[q];
    }
    __syncthreads();   // B0: B, snode, s_grab visible; prev tile epilogue done

    if (!havePre){     // cold start: gather chunk 0 now
      float4 pv0[4];
      gath_ld(Xm, isv ? 128 : 0, isv, snode[sp], tid, vt, pv0);
      gath_st(Abuf, isv, snode[sp], tid, vt, pv0);
      __syncthreads();
    }

    int nt = (t+1 < re) ? t+1 : s_grab;
    const bool hasN = (nt < total);
    int nisv=0, nbase=0, nend=0, nkey=0, nwidth=0;
    if (hasN) meta(nt, ts_tot, nisv, nbase, nend, nkey, nwidth);

    float acc[2][4][4];
    #pragma unroll
    for (int i=0;i<2;++i)
      #pragma unroll
      for (int j=0;j<4;++j)
        #pragma unroll
        for (int e=0;e<4;++e) acc[i][j][e] = 0.f;

    for (int kc = 0; kc < 4; ++kc){
      if (kc > 0) __syncthreads();   // STS of chunk kc visible; buf (kc+1)&1 free

      // ---- prefetch (chunk kc+1 of this tile, or chunk 0 of next tile) ----
      float4 pv[4];
      const bool doPre = (kc < 3) || hasN;
      const float* psrc; int pcb, pisv; const int* psn;
      if (kc < 3){
        int nk = kc + 1;
        psrc = (nk < 2) ? Xm : Xf;
        pisv = isv;
        pcb  = isv ? 128 + (nk & 1)*192 : (nk & 1)*64;
        psn  = snode[sp];
      } else {
        psrc = Xm; pisv = nisv; pcb = nisv ? 128 : 0; psn = snode[sp^1];
      }
      if (doPre) gath_ld(psrc, pcb, pisv, psn, tid, vt, pv);

      if (kc == 2 && hasN && tid < nwidth)
        snode[sp^1][tid] = (nbase + tid < nend) ? g_perm[nbase + tid] : -1;

      // ---- MMA on chunk kc ----
      const unsigned Ac = Ab + (unsigned)((kc & 1)*A_BYTES);
      const unsigned Bk = smb + (unsigned)(kc*A_BYTES);
      #pragma unroll
      for (int ks = 0; ks < 4; ++ks){
        const int k0 = ks*16;
        unsigned af[2][4], bf[2][4];
        ldsm4(af[0], Ac + (unsigned)((wm*32      + ra)*144 + (k0+ca)*2));
        ldsm4(af[1], Ac + (unsigned)((wm*32 + 16 + ra)*144 + (k0+ca)*2));
        ldsm4(bf[0], Bk + (unsigned)((wn*32      + rb)*144 + (k0+cb2)*2));
        ldsm4(bf[1], Bk + (unsigned)((wn*32 + 16 + rb)*144 + (k0+cb2)*2));
        #pragma unroll
        for (int mi = 0; mi < 2; ++mi){
          hmma(acc[mi][0], af[mi], bf[0][0], bf[0][1]);
          hmma(acc[mi][1], af[mi], bf[0][2], bf[0][3]);
          hmma(acc[mi][2], af[mi], bf[1][0], bf[1][1]);
          hmma(acc[mi][3], af[mi], bf[1][2], bf[1][3]);
        }
      }

      if (doPre)
        gath_st(Abuf + ((kc+1) & 1)*A_BYTES, pisv, psn, tid, vt, pv);
    }
    // no barrier needed here: acc is in registers; STS0' visibility handled by next B0

    // ---- epilogue ----
    if (!isv){
      // direct register -> global stores (32B-sector aligned float2 per 4 lanes)
      #pragma unroll
      for (int mi = 0; mi < 2; ++mi){
        int r0 = wm*32 + mi*16 + g4;
        int n0 = snode[sp][r0], n1 = snode[sp][r0+8];
        #pragma unroll
        for (int jj = 0; jj < 4; ++jj){
          int c = wn*32 + jj*8 + 2*t4;
          if (n0 >= 0)
            *(float2*)(out + (size_t)n0*512 + c) = make_float2(acc[mi][jj][0], acc[mi][jj][1]);
          if (n1 >= 0)
            *(float2*)(out + (size_t)n1*512 + c) = make_float2(acc[mi][jj][2], acc[mi][jj][3]);
        }
      }
    } else {
      // staged transpose for the x-interleaved v layout
      #pragma unroll
      for (int mi = 0; mi < 2; ++mi){
        int r = wm*32 + mi*16 + g4;
        #pragma unroll
        for (int jj = 0; jj < 4; ++jj){
          int c = wn*32 + jj*8 + 2*t4;
          float* d1 = stage + r*132 + c;
          d1[0] = acc[mi][jj][0]; d1[1] = acc[mi][jj][1];
          float* d2 = stage + (r+8)*132 + c;
          d2[0] = acc[mi][jj][2]; d2[1] = acc[mi][jj][3];
        }
      }
      __syncthreads();   // stage ready
      #pragma unroll
      for (int i = 0; i < 8; ++i){
        int q = tid + i*512;
        if (q >= 4032) break;
        int ln = q / 96, u = (q - ln*96) << 2;
        int node = snode[sp][ln];
        if (node < 0) continue;
        float4 v;
        float* vp = (float*)&v;
        #pragma unroll
        for (int e=0;e<4;++e){
          int jr = u + e;
          int ol = jr/3, x = jr - 3*ol;
          vp[e] = stage[(3*ln + x)*132 + ol];
        }
        *(float4*)(out + (size_t)node*512 + 128 + u) = v;
      }
    }

    // ---- advance (next B0 guards stage/snode/buf reuse) ----
    havePre = hasN;
    sp ^= 1;
    if (t+1 < re){ t = t+1; }
    else { rs = nt; re = rs + CHUNK; if (re > total) re = total; t = nt; }
  }
}

extern "C" void kernel_launch(void* const* d_in, const int* in_sizes, int n_in,
                              void* d_out, int out_size){
  const float* m_i   = (const float*)d_in[0];
  const float* nfeat = (const float*)d_in[1];
  const float* attrs = (const float*)d_in[2];
  const float* Wl0   = (const float*)d_in[3];
  const float* Wl1   = (const float*)d_in[4];
  const float* Wt0   = (const float*)d_in[5];
  const float* Wt1   = (const float*)d_in[6];
  float* out = (float*)d_out;
  int N = in_sizes[0] / 512;
  if (N > MAXN) return;

  cudaFuncSetAttribute(k_main, cudaFuncAttributeMaxDynamicSharedMemorySize, SMEM_BYTES);

  k_prepw<<<(20*32768 + 255)/256, 256>>>(Wl0, Wl1, Wt0, Wt1);
  k_zero<<<1, 32>>>();
  k_hist<<<(N + 255)/256, 256>>>(attrs, N);
  k_scan<<<1, 1>>>();
  k_scatter<<<(N + 255)/256, 256>>>(N);
  k_main<<<148, 512, SMEM_BYTES>>>(m_i, nfeat, out);
}

// round 9
// speedup vs baseline: 1.2519x; 1.0434x over previous
#include <cuda_runtime.h>
#include <cuda_fp16.h>

#define NAB 10
#define MAXN 131072
#define CHUNK 1
#define PREPW_BLOCKS 2560

static __device__ int g_cnt[NAB];
static __device__ int g_off[NAB+1];
static __device__ int g_cursor[NAB];
static __device__ int g_tb_s[NAB+1];
static __device__ int g_tb_v[NAB+1];
static __device__ int g_zn[MAXN];
static __device__ int g_perm[MAXN];
static __device__ int g_work;
static __device__ int g_done;
// fp16 weights: [20 mats][4 k-chunks][128 o][72 k-pad] (144B rows; pad stays 0)
static __device__ __half g_Wh[20*4*128*72];

__device__ __forceinline__ unsigned su32(const void* p){
  return (unsigned)__cvta_generic_to_shared(p);
}
__device__ __forceinline__ void ldsm4(unsigned r[4], unsigned addr){
  asm volatile("ldmatrix.sync.aligned.m8n8.x4.shared.b16 {%0,%1,%2,%3}, [%4];"
    : "=r"(r[0]),"=r"(r[1]),"=r"(r[2]),"=r"(r[3]) : "r"(addr));
}
__device__ __forceinline__ void hmma(float c[4], const unsigned a[4],
                                     unsigned b0, unsigned b1){
  asm volatile("mma.sync.aligned.m16n8k16.row.col.f32.f16.f16.f32 "
    "{%0,%1,%2,%3},{%4,%5,%6,%7},{%8,%9},{%0,%1,%2,%3};"
    : "+f"(c[0]),"+f"(c[1]),"+f"(c[2]),"+f"(c[3])
    : "r"(a[0]),"r"(a[1]),"r"(a[2]),"r"(a[3]),"r"(b0),"r"(b1));
}

// ---------- fused prep kernel: prepw + hist + (last block) scan ----------
__global__ void k_prep(const float* __restrict__ Wl0, const float* __restrict__ Wl1,
                       const float* __restrict__ Wt0, const float* __restrict__ Wt1,
                       const float* __restrict__ attrs, int N, int nblocks){
  if (blockIdx.x < PREPW_BLOCKS){
    int idx = blockIdx.x*blockDim.x + threadIdx.x;   // < 20*32768
    int mat = idx >> 15;
    int r = idx & 32767;
    int k = r >> 7, o = r & 127;
    int type = mat / 10, a = mat - type*10;
    float v;
    if (k < 128) {
      const float* W = type ? Wl1 : Wl0;
      v = W[k*128 + o] * 0.08838834764831845f;                 // LIN: 1/sqrt(128)
    } else {
      const float* W = type ? Wt1 : Wt0;
      v = W[(k-128)*1280 + a*128 + o] * 0.027950849718747373f; // TP: 1/sqrt(1280)
    }
    int kc = k >> 6, kk = k & 63;
    g_Wh[(size_t)mat*36864 + kc*9216 + o*72 + kk] = __float2half_rn(v);
  } else {
    __shared__ int s[NAB];
    if (threadIdx.x < NAB) s[threadIdx.x] = 0;
    __syncthreads();
    int n = (blockIdx.x - PREPW_BLOCKS)*blockDim.x + threadIdx.x;
    if (n < N){
      const float* p = attrs + (size_t)n*NAB;
      int a = 0; float best = p[0];
      #pragma unroll
      for (int i=1;i<NAB;++i){ float v=p[i]; if (v>best){best=v;a=i;} }
      g_zn[n] = a;
      atomicAdd(&s[a], 1);
    }
    __syncthreads();
    if (threadIdx.x < NAB) atomicAdd(&g_cnt[threadIdx.x], s[threadIdx.x]);
  }
  __syncthreads();
  if (threadIdx.x == 0){
    __threadfence();
    if (atomicAdd(&g_done, 1) == nblocks - 1){
      // last block: scan + reset counters for the next (deterministic) call
      g_work = 0;
      g_done = 0;
      g_off[0]=0; g_tb_s[0]=0; g_tb_v[0]=0;
      for (int a=0;a<NAB;++a){
        int c = g_cnt[a];
        g_cnt[a] = 0;
        g_off[a+1]  = g_off[a] + c;
        g_cursor[a] = g_off[a];
        g_tb_s[a+1] = g_tb_s[a] + (c + 127)/128;
        g_tb_v[a+1] = g_tb_v[a] + (c + 41)/42;
      }
      __threadfence();
    }
  }
}

__global__ void k_scatter(int N){
  __shared__ int sc[NAB], sb[NAB];
  if (threadIdx.x < NAB) sc[threadIdx.x] = 0;
  __syncthreads();
  int n = blockIdx.x*blockDim.x + threadIdx.x;
  int a = 0, p = 0;
  bool valid = (n < N);
  if (valid){ a = g_zn[n]; p = atomicAdd(&sc[a], 1); }
  __syncthreads();
  if (threadIdx.x < NAB) sb[threadIdx.x] = atomicAdd(&g_cursor[threadIdx.x], sc[threadIdx.x]);
  __syncthreads();
  if (valid) g_perm[sb[a] + p] = n;
}

// ---------- main kernel helpers ----------
struct VTab { int ln[4]; int u[4]; unsigned off[4][4]; };

__device__ __forceinline__ void meta(int t, int ts_tot,
    int& isv, int& base, int& end, int& key, int& width){
  isv = (t >= ts_tot) ? 1 : 0;
  int tt = isv ? t - ts_tot : t;
  const int* tb = isv ? g_tb_v : g_tb_s;
  int a = 0;
  while (tt >= tb[a+1]) ++a;
  int tile = tt - tb[a];
  width = isv ? 42 : 128;
  base = g_off[a] + tile*width;
  end  = g_off[a+1];
  key  = (isv ? NAB : 0) + a;
}

__device__ __forceinline__ void gath_ld(const float* __restrict__ src, int cb, int isv,
                                        const int* sn, int tid, const VTab& vt, float4 pv[4]){
  if (!isv){
    #pragma unroll
    for (int i=0;i<4;++i){
      int q = tid + i*512;
      int ln = q>>4, u=(q&15)<<2;
      int node = sn[ln];
      if (node>=0) pv[i] = *(const float4*)(src + (size_t)node*512 + cb + u);
    }
  } else {
    #pragma unroll
    for (int i=0;i<4;++i){
      if (vt.ln[i] < 0) continue;
      int node = sn[vt.ln[i]];
      if (node>=0) pv[i] = *(const float4*)(src + (size_t)node*512 + cb + vt.u[i]);
    }
  }
}
__device__ __forceinline__ void gath_st(char* Ad, int isv, const int* sn, int tid,
                                        const VTab& vt, const float4 pv[4]){
  if (!isv){
    #pragma unroll
    for (int i=0;i<4;++i){
      int q = tid + i*512;
      int ln = q>>4, u=(q&15)<<2;
      if (sn[ln] < 0) continue;
      __half2* d = (__half2*)(Ad + ln*144 + u*2);
      d[0] = __floats2half2_rn(pv[i].x, pv[i].y);
      d[1] = __floats2half2_rn(pv[i].z, pv[i].w);
    }
  } else {
    #pragma unroll
    for (int i=0;i<4;++i){
      if (vt.ln[i] < 0) continue;
      if (sn[vt.ln[i]] < 0) continue;
      const float vv[4] = {pv[i].x, pv[i].y, pv[i].z, pv[i].w};
      #pragma unroll
      for (int e=0;e<4;++e)
        *(__half*)(Ad + vt.off[i][e]) = __float2half_rn(vv[e]);
    }
  }
}

// ---------- main kernel ----------
// SMEM: [0, 73728)             B weights: 4 chunks x [128 o][72 halves] (144B rows)
//       [73728, 73728+36864)   A double buffer: 2 x [128 m][72 halves]
//       [110592, 110592+67584) C stage [128][132] fp32 (v-tiles only)
#define B_BYTES   73728
#define A_BYTES   18432
#define STAGE_OFF (B_BYTES + 2*A_BYTES)
#define SMEM_BYTES (STAGE_OFF + 128*132*4)

__global__ void __launch_bounds__(512) k_main(
    const float* __restrict__ Xm, const float* __restrict__ Xf,
    float* __restrict__ out){
  extern __shared__ char smem[];
  char*  Abuf  = smem + B_BYTES;
  float* stage = (float*)(smem + STAGE_OFF);
  __shared__ int snode[2][128];
  __shared__ int s_grab;

  const int tid  = threadIdx.x;
  const int lane = tid & 31;
  const int wid  = tid >> 5;
  const int wm = wid & 3, wn = wid >> 2;   // 4x4 warps, each 32 rows x 32 cols
  const int g4 = lane >> 2, t4 = lane & 3;
  const unsigned smb = su32(smem);
  const unsigned Ab  = smb + B_BYTES;

  const int ra  = lane & 15;
  const int ca  = (lane >> 4) << 3;
  const int rb  = ((lane >> 4) & 1)*8 + (lane & 7);
  const int cb2 = ((lane >> 3) & 1) << 3;

  // per-thread v-gather index tables (loop-invariant)
  VTab vt;
  #pragma unroll
  for (int i=0;i<4;++i){
    int q = tid + i*512;
    if (q < 2016){
      int ln = q/48, u = (q - ln*48) << 2;
      vt.ln[i] = ln; vt.u[i] = u;
      #pragma unroll
      for (int e=0;e<4;++e){
        int jr = u + e;
        int il = jr/3, x = jr - 3*il;
        vt.off[i][e] = (unsigned)((3*ln + x)*144 + il*2);
      }
    } else {
      vt.ln[i] = -1; vt.u[i] = 0;
      #pragma unroll
      for (int e=0;e<4;++e) vt.off[i][e] = 0;
    }
  }

  const int ts_tot = g_tb_s[NAB];
  const int tv_tot = g_tb_v[NAB];
  const int total  = ts_tot + tv_tot;

  if (tid == 0) s_grab = atomicAdd(&g_work, CHUNK);
  __syncthreads();
  int rs = s_grab;
  int re = rs + CHUNK; if (re > total) re = total;
  int t = rs;
  int cur = -1, sp = 0;
  bool havePre = false;

  while (t < total){
    int isv, base, end, key, width;
    meta(t, ts_tot, isv, base, end, key, width);
    if (t == re-1 && tid == 0) s_grab = atomicAdd(&g_work, CHUNK);
    if (!havePre && tid < width)
      snode[sp][tid] = (base + tid < end) ? g_perm[base + tid] : -1;
    if (key != cur){
      cur = key;
      const float4* srcW = (const float4*)(g_Wh + (size_t)key*36864);
      float4* dstW = (float4*)smem;
      #pragma unroll 3
      for (int q = tid; q < 4608; q += 512) dstW[q] = srcW[q];
    }
    __syncthreads();   // B0: B, snode, s_grab visible; prev tile epilogue done

    if (!havePre){     // cold start: gather chunk 0 now
      float4 pv0[4];
      gath_ld(Xm, isv ? 128 : 0, isv, snode[sp], tid, vt, pv0);
      gath_st(Abuf, isv, snode[sp], tid, vt, pv0);
      __syncthreads();
    }

    int nt = (t+1 < re) ? t+1 : s_grab;
    const bool hasN = (nt < total);
    int nisv=0, nbase=0, nend=0, nkey=0, nwidth=0;
    if (hasN) meta(nt, ts_tot, nisv, nbase, nend, nkey, nwidth);

    float acc[2][4][4];
    #pragma unroll
    for (int i=0;i<2;++i)
      #pragma unroll
      for (int j=0;j<4;++j)
        #pragma unroll
        for (int e=0;e<4;++e) acc[i][j][e] = 0.f;

    for (int kc = 0; kc < 4; ++kc){
      if (kc > 0) __syncthreads();   // STS of chunk kc visible; buf (kc+1)&1 free

      // ---- prefetch (chunk kc+1 of this tile, or chunk 0 of next tile) ----
      float4 pv[4];
      const bool doPre = (kc < 3) || hasN;
      const float* psrc; int pcb, pisv; const int* psn;
      if (kc < 3){
        int nk = kc + 1;
        psrc = (nk < 2) ? Xm : Xf;
        pisv = isv;
        pcb  = isv ? 128 + (nk & 1)*192 : (nk & 1)*64;
        psn  = snode[sp];
      } else {
        psrc = Xm; pisv = nisv; pcb = nisv ? 128 : 0; psn = snode[sp^1];
      }
      if (doPre) gath_ld(psrc, pcb, pisv, psn, tid, vt, pv);

      if (kc == 2 && hasN && tid < nwidth)
        snode[sp^1][tid] = (nbase + tid < nend) ? g_perm[nbase + tid] : -1;

      // ---- MMA on chunk kc ----
      const unsigned Ac = Ab + (unsigned)((kc & 1)*A_BYTES);
      const unsigned Bk = smb + (unsigned)(kc*A_BYTES);
      #pragma unroll
      for (int ks = 0; ks < 4; ++ks){
        const int k0 = ks*16;
        unsigned af[2][4], bf[2][4];
        ldsm4(af[0], Ac + (unsigned)((wm*32      + ra)*144 + (k0+ca)*2));
        ldsm4(af[1], Ac + (unsigned)((wm*32 + 16 + ra)*144 + (k0+ca)*2));
        ldsm4(bf[0], Bk + (unsigned)((wn*32      + rb)*144 + (k0+cb2)*2));
        ldsm4(bf[1], Bk + (unsigned)((wn*32 + 16 + rb)*144 + (k0+cb2)*2));
        #pragma unroll
        for (int mi = 0; mi < 2; ++mi){
          hmma(acc[mi][0], af[mi], bf[0][0], bf[0][1]);
          hmma(acc[mi][1], af[mi], bf[0][2], bf[0][3]);
          hmma(acc[mi][2], af[mi], bf[1][0], bf[1][1]);
          hmma(acc[mi][3], af[mi], bf[1][2], bf[1][3]);
        }
      }

      if (doPre)
        gath_st(Abuf + ((kc+1) & 1)*A_BYTES, pisv, psn, tid, vt, pv);
    }
    // no barrier needed here: acc is in registers; STS0' visibility handled by next B0

    // ---- epilogue ----
    if (!isv){
      // direct register -> global stores (32B-sector aligned float2 per 4 lanes)
      #pragma unroll
      for (int mi = 0; mi < 2; ++mi){
        int r0 = wm*32 + mi*16 + g4;
        int n0 = snode[sp][r0], n1 = snode[sp][r0+8];
        #pragma unroll
        for (int jj = 0; jj < 4; ++jj){
          int c = wn*32 + jj*8 + 2*t4;
          if (n0 >= 0)
            *(float2*)(out + (size_t)n0*512 + c) = make_float2(acc[mi][jj][0], acc[mi][jj][1]);
          if (n1 >= 0)
            *(float2*)(out + (size_t)n1*512 + c) = make_float2(acc[mi][jj][2], acc[mi][jj][3]);
        }
      }
    } else {
      // staged transpose for the x-interleaved v layout
      #pragma unroll
      for (int mi = 0; mi < 2; ++mi){
        int r = wm*32 + mi*16 + g4;
        #pragma unroll
        for (int jj = 0; jj < 4; ++jj){
          int c = wn*32 + jj*8 + 2*t4;
          float* d1 = stage + r*132 + c;
          d1[0] = acc[mi][jj][0]; d1[1] = acc[mi][jj][1];
          float* d2 = stage + (r+8)*132 + c;
          d2[0] = acc[mi][jj][2]; d2[1] = acc[mi][jj][3];
        }
      }
      __syncthreads();   // stage ready
      #pragma unroll
      for (int i = 0; i < 8; ++i){
        int q = tid + i*512;
        if (q >= 4032) break;
        int ln = q / 96, u = (q - ln*96) << 2;
        int node = snode[sp][ln];
        if (node < 0) continue;
        float4 v;
        float* vp = (float*)&v;
        #pragma unroll
        for (int e=0;e<4;++e){
          int jr = u + e;
          int ol = jr/3, x = jr - 3*ol;
          vp[e] = stage[(3*ln + x)*132 + ol];
        }
        *(float4*)(out + (size_t)node*512 + 128 + u) = v;
      }
    }

    // ---- advance (next B0 guards stage/snode/buf reuse) ----
    havePre = hasN;
    sp ^= 1;
    if (t+1 < re){ t = t+1; }
    else { rs = nt; re = rs + CHUNK; if (re > total) re = total; t = nt; }
  }
}

extern "C" void kernel_launch(void* const* d_in, const int* in_sizes, int n_in,
                              void* d_out, int out_size){
  const float* m_i   = (const float*)d_in[0];
  const float* nfeat = (const float*)d_in[1];
  const float* attrs = (const float*)d_in[2];
  const float* Wl0   = (const float*)d_in[3];
  const float* Wl1   = (const float*)d_in[4];
  const float* Wt0   = (const float*)d_in[5];
  const float* Wt1   = (const float*)d_in[6];
  float* out = (float*)d_out;
  int N = in_sizes[0] / 512;
  if (N > MAXN) return;

  cudaFuncSetAttribute(k_main, cudaFuncAttributeMaxDynamicSharedMemorySize, SMEM_BYTES);

  int hist_blocks = (N + 255)/256;
  int prep_blocks = PREPW_BLOCKS + hist_blocks;
  k_prep<<<prep_blocks, 256>>>(Wl0, Wl1, Wt0, Wt1, attrs, N, prep_blocks);
  k_scatter<<<hist_blocks, 256>>>(N);
  k_main<<<148, 512, SMEM_BYTES>>>(m_i, nfeat, out);
}

// round 10
// speedup vs baseline: 1.2673x; 1.0123x over previous
#include <cuda_runtime.h>
#include <cuda_fp16.h>

#define NAB 10
#define MAXN 131072
#define GRID 148
#define NTHR 512

static __device__ int g_cnt[NAB];
static __device__ int g_off[NAB+1];
static __device__ int g_cursor[NAB];
static __device__ int g_tb_s[NAB+1];
static __device__ int g_tb_v[NAB+1];
static __device__ int g_zn[MAXN];
static __device__ int g_perm[MAXN];
static __device__ int g_work;
static __device__ int g_b1, g_b2, g_b3, g_fin;
// fp16 weights: [20 mats][4 k-chunks][128 o][72 k-pad] (144B rows; pad stays 0)
static __device__ __half g_Wh[20*4*128*72];

__device__ __forceinline__ unsigned su32(const void* p){
  return (unsigned)__cvta_generic_to_shared(p);
}
__device__ __forceinline__ void ldsm4(unsigned r[4], unsigned addr){
  asm volatile("ldmatrix.sync.aligned.m8n8.x4.shared.b16 {%0,%1,%2,%3}, [%4];"
    : "=r"(r[0]),"=r"(r[1]),"=r"(r[2]),"=r"(r[3]) : "r"(addr));
}
__device__ __forceinline__ void hmma(float c[4], const unsigned a[4],
                                     unsigned b0, unsigned b1){
  asm volatile("mma.sync.aligned.m16n8k16.row.col.f32.f16.f16.f32 "
    "{%0,%1,%2,%3},{%4,%5,%6,%7},{%8,%9},{%0,%1,%2,%3};"
    : "+f"(c[0]),"+f"(c[1]),"+f"(c[2]),"+f"(c[3])
    : "r"(a[0]),"r"(a[1]),"r"(a[2]),"r"(a[3]),"r"(b0),"r"(b1));
}
__device__ __forceinline__ void gbar(int* c){
  __syncthreads();
  if (threadIdx.x == 0){
    __threadfence();
    atomicAdd(c, 1);
    while (*(volatile int*)c < GRID) __nanosleep(64);
  }
  __syncthreads();
}

// ---------- main kernel helpers ----------
struct VTab { int ln[4]; int u[4]; unsigned off[4][4]; };

__device__ __forceinline__ void meta(int t, int ts_tot,
    int& isv, int& base, int& end, int& key, int& width){
  isv = (t >= ts_tot) ? 1 : 0;
  int tt = isv ? t - ts_tot : t;
  const int* tb = isv ? g_tb_v : g_tb_s;
  int a = 0;
  while (tt >= tb[a+1]) ++a;
  int tile = tt - tb[a];
  width = isv ? 42 : 128;
  base = g_off[a] + tile*width;
  end  = g_off[a+1];
  key  = (isv ? NAB : 0) + a;
}

__device__ __forceinline__ void gath_ld(const float* __restrict__ src, int cb, int isv,
                                        const int* sn, int tid, const VTab& vt, float4 pv[4]){
  if (!isv){
    #pragma unroll
    for (int i=0;i<4;++i){
      int q = tid + i*512;
      int ln = q>>4, u=(q&15)<<2;
      int node = sn[ln];
      if (node>=0) pv[i] = *(const float4*)(src + (size_t)node*512 + cb + u);
    }
  } else {
    #pragma unroll
    for (int i=0;i<4;++i){
      if (vt.ln[i] < 0) continue;
      int node = sn[vt.ln[i]];
      if (node>=0) pv[i] = *(const float4*)(src + (size_t)node*512 + cb + vt.u[i]);
    }
  }
}
__device__ __forceinline__ void gath_st(char* Ad, int isv, const int* sn, int tid,
                                        const VTab& vt, const float4 pv[4]){
  if (!isv){
    #pragma unroll
    for (int i=0;i<4;++i){
      int q = tid + i*512;
      int ln = q>>4, u=(q&15)<<2;
      if (sn[ln] < 0) continue;
      __half2* d = (__half2*)(Ad + ln*144 + u*2);
      d[0] = __floats2half2_rn(pv[i].x, pv[i].y);
      d[1] = __floats2half2_rn(pv[i].z, pv[i].w);
    }
  } else {
    #pragma unroll
    for (int i=0;i<4;++i){
      if (vt.ln[i] < 0) continue;
      if (sn[vt.ln[i]] < 0) continue;
      const float vv[4] = {pv[i].x, pv[i].y, pv[i].z, pv[i].w};
      #pragma unroll
      for (int e=0;e<4;++e)
        *(__half*)(Ad + vt.off[i][e]) = __float2half_rn(vv[e]);
    }
  }
}

// ---------- the one kernel ----------
// SMEM: [0, 73728)             B weights: 4 chunks x [128 o][72 halves] (144B rows)
//       [73728, 73728+36864)   A double buffer: 2 x [128 m][72 halves]
//       [110592, 110592+67584) C stage [128][132] fp32 (v-tiles only)
#define B_BYTES   73728
#define A_BYTES   18432
#define STAGE_OFF (B_BYTES + 2*A_BYTES)
#define SMEM_BYTES (STAGE_OFF + 128*132*4)

__global__ void __launch_bounds__(512) k_all(
    const float* __restrict__ Xm, const float* __restrict__ Xf,
    const float* __restrict__ attrs,
    const float* __restrict__ Wl0, const float* __restrict__ Wl1,
    const float* __restrict__ Wt0, const float* __restrict__ Wt1,
    float* __restrict__ out, int N){
  extern __shared__ char smem[];
  char*  Abuf  = smem + B_BYTES;
  float* stage = (float*)(smem + STAGE_OFF);
  __shared__ int snode[2][128];
  __shared__ int s_grab;
  __shared__ int s_cnt[NAB], s_base[NAB];

  const int tid  = threadIdx.x;
  const int bid  = blockIdx.x;
  const int gthr = bid*NTHR + tid;

  // ===== Phase A: weight prep (grid-strided) =====
  for (int idx = gthr; idx < 20*32768; idx += GRID*NTHR){
    int mat = idx >> 15;
    int r = idx & 32767;
    int k = r >> 7, o = r & 127;
    int type = mat / 10, a = mat - type*10;
    float v;
    if (k < 128) {
      const float* W = type ? Wl1 : Wl0;
      v = W[k*128 + o] * 0.08838834764831845f;                 // LIN: 1/sqrt(128)
    } else {
      const float* W = type ? Wt1 : Wt0;
      v = W[(k-128)*1280 + a*128 + o] * 0.027950849718747373f; // TP: 1/sqrt(1280)
    }
    int kc = k >> 6, kk = k & 63;
    g_Wh[(size_t)mat*36864 + kc*9216 + o*72 + kk] = __float2half_rn(v);
  }

  // ===== Phase B: hist (SMEM-aggregated) =====
  if (tid < NAB) s_cnt[tid] = 0;
  __syncthreads();
  for (int n = gthr; n < N; n += GRID*NTHR){
    const float* p = attrs + (size_t)n*NAB;
    int a = 0; float best = p[0];
    #pragma unroll
    for (int i=1;i<NAB;++i){ float v=p[i]; if (v>best){best=v;a=i;} }
    g_zn[n] = a;
    atomicAdd(&s_cnt[a], 1);
  }
  __syncthreads();
  if (tid < NAB) atomicAdd(&g_cnt[tid], s_cnt[tid]);

  gbar(&g_b1);     // all hist/prep done
  if (bid == 0 && tid == 0){
    g_off[0]=0; g_tb_s[0]=0; g_tb_v[0]=0;
    for (int a=0;a<NAB;++a){
      int c = g_cnt[a];
      g_off[a+1]  = g_off[a] + c;
      g_cursor[a] = g_off[a];
      g_tb_s[a+1] = g_tb_s[a] + (c + 127)/128;
      g_tb_v[a+1] = g_tb_v[a] + (c + 41)/42;
    }
    __threadfence();
  }
  gbar(&g_b2);     // scan visible

  // ===== Phase C: scatter (per-CTA SMEM aggregation) =====
  for (int n0 = bid*NTHR; n0 < N; n0 += GRID*NTHR){
    int n = n0 + tid;
    __syncthreads();
    if (tid < NAB) s_cnt[tid] = 0;
    __syncthreads();
    int a = 0, p = 0;
    bool valid = (n < N);
    if (valid){ a = g_zn[n]; p = atomicAdd(&s_cnt[a], 1); }
    __syncthreads();
    if (tid < NAB) s_base[tid] = atomicAdd(&g_cursor[tid], s_cnt[tid]);
    __syncthreads();
    if (valid) g_perm[s_base[a] + p] = n;
  }
  gbar(&g_b3);     // perm complete

  // ===== Phase D: tiled GEMM (unchanged core) =====
  const int lane = tid & 31;
  const int wid  = tid >> 5;
  const int wm = wid & 3, wn = wid >> 2;   // 4x4 warps, each 32 rows x 32 cols
  const int g4 = lane >> 2, t4 = lane & 3;
  const unsigned smb = su32(smem);
  const unsigned Ab  = smb + B_BYTES;

  const int ra  = lane & 15;
  const int ca  = (lane >> 4) << 3;
  const int rb  = ((lane >> 4) & 1)*8 + (lane & 7);
  const int cb2 = ((lane >> 3) & 1) << 3;

  VTab vt;
  #pragma unroll
  for (int i=0;i<4;++i){
    int q = tid + i*512;
    if (q < 2016){
      int ln = q/48, u = (q - ln*48) << 2;
      vt.ln[i] = ln; vt.u[i] = u;
      #pragma unroll
      for (int e=0;e<4;++e){
        int jr = u + e;
        int il = jr/3, x = jr - 3*il;
        vt.off[i][e] = (unsigned)((3*ln + x)*144 + il*2);
      }
    } else {
      vt.ln[i] = -1; vt.u[i] = 0;
      #pragma unroll
      for (int e=0;e<4;++e) vt.off[i][e] = 0;
    }
  }

  const int ts_tot = g_tb_s[NAB];
  const int tv_tot = g_tb_v[NAB];
  const int total  = ts_tot + tv_tot;

  if (tid == 0) s_grab = atomicAdd(&g_work, 1);
  __syncthreads();
  int t = s_grab;
  int cur = -1, sp = 0;
  bool havePre = false;

  while (t < total){
    int isv, base, end, key, width;
    meta(t, ts_tot, isv, base, end, key, width);
    if (tid == 0) s_grab = atomicAdd(&g_work, 1);
    if (!havePre && tid < width)
      snode[sp][tid] = (base + tid < end) ? g_perm[base + tid] : -1;
    if (key != cur){
      cur = key;
      const float4* srcW = (const float4*)(g_Wh + (size_t)key*36864);
      float4* dstW = (float4*)smem;
      #pragma unroll 3
      for (int q = tid; q < 4608; q += 512) dstW[q] = srcW[q];
    }
    __syncthreads();   // B0: B, snode, s_grab visible; prev tile epilogue done

    if (!havePre){     // cold start: gather chunk 0 now
      float4 pv0[4];
      gath_ld(Xm, isv ? 128 : 0, isv, snode[sp], tid, vt, pv0);
      gath_st(Abuf, isv, snode[sp], tid, vt, pv0);
      __syncthreads();
    }

    int nt = s_grab;
    const bool hasN = (nt < total);
    int nisv=0, nbase=0, nend=0, nkey=0, nwidth=0;
    if (hasN) meta(nt, ts_tot, nisv, nbase, nend, nkey, nwidth);

    float acc[2][4][4];
    #pragma unroll
    for (int i=0;i<2;++i)
      #pragma unroll
      for (int j=0;j<4;++j)
        #pragma unroll
        for (int e=0;e<4;++e) acc[i][j][e] = 0.f;

    for (int kc = 0; kc < 4; ++kc){
      if (kc > 0) __syncthreads();   // STS of chunk kc visible; buf (kc+1)&1 free

      // ---- prefetch (chunk kc+1 of this tile, or chunk 0 of next tile) ----
      float4 pv[4];
      const bool doPre = (kc < 3) || hasN;
      const float* psrc; int pcb, pisv; const int* psn;
      if (kc < 3){
        int nk = kc + 1;
        psrc = (nk < 2) ? Xm : Xf;
        pisv = isv;
        pcb  = isv ? 128 + (nk & 1)*192 : (nk & 1)*64;
        psn  = snode[sp];
      } else {
        psrc = Xm; pisv = nisv; pcb = nisv ? 128 : 0; psn = snode[sp^1];
      }
      if (doPre) gath_ld(psrc, pcb, pisv, psn, tid, vt, pv);

      if (kc == 2 && hasN && tid < nwidth)
        snode[sp^1][tid] = (nbase + tid < nend) ? g_perm[nbase + tid] : -1;

      // ---- MMA on chunk kc ----
      const unsigned Ac = Ab + (unsigned)((kc & 1)*A_BYTES);
      const unsigned Bk = smb + (unsigned)(kc*A_BYTES);
      #pragma unroll
      for (int ks = 0; ks < 4; ++ks){
        const int k0 = ks*16;
        unsigned af[2][4], bf[2][4];
        ldsm4(af[0], Ac + (unsigned)((wm*32      + ra)*144 + (k0+ca)*2));
        ldsm4(af[1], Ac + (unsigned)((wm*32 + 16 + ra)*144 + (k0+ca)*2));
        ldsm4(bf[0], Bk + (unsigned)((wn*32      + rb)*144 + (k0+cb2)*2));
        ldsm4(bf[1], Bk + (unsigned)((wn*32 + 16 + rb)*144 + (k0+cb2)*2));
        #pragma unroll
        for (int mi = 0; mi < 2; ++mi){
          hmma(acc[mi][0], af[mi], bf[0][0], bf[0][1]);
          hmma(acc[mi][1], af[mi], bf[0][2], bf[0][3]);
          hmma(acc[mi][2], af[mi], bf[1][0], bf[1][1]);
          hmma(acc[mi][3], af[mi], bf[1][2], bf[1][3]);
        }
      }

      if (doPre)
        gath_st(Abuf + ((kc+1) & 1)*A_BYTES, pisv, psn, tid, vt, pv);
    }

    // ---- epilogue ----
    if (!isv){
      #pragma unroll
      for (int mi = 0; mi < 2; ++mi){
        int r0 = wm*32 + mi*16 + g4;
        int n0 = snode[sp][r0], n1 = snode[sp][r0+8];
        #pragma unroll
        for (int jj = 0; jj < 4; ++jj){
          int c = wn*32 + jj*8 + 2*t4;
          if (n0 >= 0)
            *(float2*)(out + (size_t)n0*512 + c) = make_float2(acc[mi][jj][0], acc[mi][jj][1]);
          if (n1 >= 0)
            *(float2*)(out + (size_t)n1*512 + c) = make_float2(acc[mi][jj][2], acc[mi][jj][3]);
        }
      }
    } else {
      #pragma unroll
      for (int mi = 0; mi < 2; ++mi){
        int r = wm*32 + mi*16 + g4;
        #pragma unroll
        for (int jj = 0; jj < 4; ++jj){
          int c = wn*32 + jj*8 + 2*t4;
          float* d1 = stage + r*132 + c;
          d1[0] = acc[mi][jj][0]; d1[1] = acc[mi][jj][1];
          float* d2 = stage + (r+8)*132 + c;
          d2[0] = acc[mi][jj][2]; d2[1] = acc[mi][jj][3];
        }
      }
      __syncthreads();   // stage ready
      #pragma unroll
      for (int i = 0; i < 8; ++i){
        int q = tid + i*512;
        if (q >= 4032) break;
        int ln = q / 96, u = (q - ln*96) << 2;
        int node = snode[sp][ln];
        if (node < 0) continue;
        float4 v;
        float* vp = (float*)&v;
        #pragma unroll
        for (int e=0;e<4;++e){
          int jr = u + e;
          int ol = jr/3, x = jr - 3*ol;
          vp[e] = stage[(3*ln + x)*132 + ol];
        }
        *(float4*)(out + (size_t)node*512 + 128 + u) = v;
      }
    }

    havePre = hasN;
    sp ^= 1;
    t = nt;
  }

  // ===== reset globals for next (deterministic) replay =====
  __syncthreads();
  if (tid == 0){
    __threadfence();
    if (atomicAdd(&g_fin, 1) == GRID - 1){
      g_work = 0; g_fin = 0; g_b1 = 0; g_b2 = 0; g_b3 = 0;
      for (int a=0;a<NAB;++a) g_cnt[a] = 0;
      __threadfence();
    }
  }
}

extern "C" void kernel_launch(void* const* d_in, const int* in_sizes, int n_in,
                              void* d_out, int out_size){
  const float* m_i   = (const float*)d_in[0];
  const float* nfeat = (const float*)d_in[1];
  const float* attrs = (const float*)d_in[2];
  const float* Wl0   = (const float*)d_in[3];
  const float* Wl1   = (const float*)d_in[4];
  const float* Wt0   = (const float*)d_in[5];
  const float* Wt1   = (const float*)d_in[6];
  float* out = (float*)d_out;
  int N = in_sizes[0] / 512;
  if (N > MAXN) return;

  cudaFuncSetAttribute(k_all, cudaFuncAttributeMaxDynamicSharedMemorySize, SMEM_BYTES);
  k_all<<<GRID, NTHR, SMEM_BYTES>>>(m_i, nfeat, attrs, Wl0, Wl1, Wt0, Wt1, out, N);
}

// round 11
// speedup vs baseline: 1.3688x; 1.0801x over previous
#include <cuda_runtime.h>
#include <cuda_fp16.h>

#define NAB 10
#define MAXN 131072
#define GRID 148
#define NTHR 512
#define CHUNK 2

static __device__ int g_cnt[NAB];
static __device__ int g_off[NAB+1];
static __device__ int g_cursor[NAB];
static __device__ int g_tb_s[NAB+1];
static __device__ int g_tb_v[NAB+1];
static __device__ int g_zn[MAXN];
static __device__ int g_perm[MAXN];
static __device__ int g_work;
static __device__ int g_b1, g_b2, g_b3, g_fin;
// fp16 weights: [20 mats][4 k-chunks][128 o][72 k-pad] (144B rows; pad stays 0)
static __device__ __half g_Wh[20*4*128*72];

__device__ __forceinline__ unsigned su32(const void* p){
  return (unsigned)__cvta_generic_to_shared(p);
}
__device__ __forceinline__ void ldsm4(unsigned r[4], unsigned addr){
  asm volatile("ldmatrix.sync.aligned.m8n8.x4.shared.b16 {%0,%1,%2,%3}, [%4];"
    : "=r"(r[0]),"=r"(r[1]),"=r"(r[2]),"=r"(r[3]) : "r"(addr));
}
__device__ __forceinline__ void hmma(float c[4], const unsigned a[4],
                                     unsigned b0, unsigned b1){
  asm volatile("mma.sync.aligned.m16n8k16.row.col.f32.f16.f16.f32 "
    "{%0,%1,%2,%3},{%4,%5,%6,%7},{%8,%9},{%0,%1,%2,%3};"
    : "+f"(c[0]),"+f"(c[1]),"+f"(c[2]),"+f"(c[3])
    : "r"(a[0]),"r"(a[1]),"r"(a[2]),"r"(a[3]),"r"(b0),"r"(b1));
}
__device__ __forceinline__ void gbar(int* c){
  __syncthreads();
  if (threadIdx.x == 0){
    __threadfence();
    atomicAdd(c, 1);
    while (*(volatile int*)c < GRID) __nanosleep(64);
  }
  __syncthreads();
}

struct VTab { int ln[4]; int u[4]; unsigned off[4][4]; };

__device__ __forceinline__ void meta(int t, int ts_tot,
    int& isv, int& base, int& end, int& key, int& width){
  isv = (t >= ts_tot) ? 1 : 0;
  int tt = isv ? t - ts_tot : t;
  const int* tb = isv ? g_tb_v : g_tb_s;
  int a = 0;
  while (tt >= tb[a+1]) ++a;
  int tile = tt - tb[a];
  width = isv ? 42 : 128;
  base = g_off[a] + tile*width;
  end  = g_off[a+1];
  key  = (isv ? NAB : 0) + a;
}

__device__ __forceinline__ void load_nd(int isv, int nbase, int nend, int tid,
                                        const VTab& vt, int nd[4]){
  if (!isv){
    #pragma unroll
    for (int i=0;i<4;++i){
      int slot = (tid + i*512)>>4;
      nd[i] = (nbase+slot < nend) ? g_perm[nbase+slot] : -1;
    }
  } else {
    #pragma unroll
    for (int i=0;i<4;++i){
      int slot = vt.ln[i];
      nd[i] = (slot>=0 && nbase+slot < nend) ? g_perm[nbase+slot] : -1;
    }
  }
}

__device__ __forceinline__ void gath_ld2(const float* __restrict__ src, int cb, int isv,
                                         const int nd[4], int tid, const VTab& vt, float4 pv[4]){
  if (!isv){
    #pragma unroll
    for (int i=0;i<4;++i){
      int q = tid + i*512;
      int u = (q&15)<<2;
      pv[i] = (nd[i]>=0) ? *(const float4*)(src + (size_t)nd[i]*512 + cb + u)
                         : make_float4(0.f,0.f,0.f,0.f);
    }
  } else {
    #pragma unroll
    for (int i=0;i<4;++i){
      if (vt.ln[i] < 0) continue;
      pv[i] = (nd[i]>=0) ? *(const float4*)(src + (size_t)nd[i]*512 + cb + vt.u[i])
                         : make_float4(0.f,0.f,0.f,0.f);
    }
  }
}
__device__ __forceinline__ void gath_st2(char* Ad, int isv, int tid,
                                         const VTab& vt, const float4 pv[4]){
  if (!isv){
    #pragma unroll
    for (int i=0;i<4;++i){
      int q = tid + i*512;
      int ln = q>>4, u=(q&15)<<2;
      __half2* d = (__half2*)(Ad + ln*144 + u*2);
      d[0] = __floats2half2_rn(pv[i].x, pv[i].y);
      d[1] = __floats2half2_rn(pv[i].z, pv[i].w);
    }
  } else {
    #pragma unroll
    for (int i=0;i<4;++i){
      if (vt.ln[i] < 0) continue;
      const float vv[4] = {pv[i].x, pv[i].y, pv[i].z, pv[i].w};
      #pragma unroll
      for (int e=0;e<4;++e)
        *(__half*)(Ad + vt.off[i][e]) = __float2half_rn(vv[e]);
    }
  }
}

// SMEM: [0, 73728)        B weights (4 chunks x [128][72h], 144B rows)
//       [73728, +73728)   A buffer 0 (full tile, 4 chunk sections)
//       [147456, +73728)  A buffer 1
// v epilogue stage [128][132] f32 reuses the DEAD current-tile A buffer.
#define B_BYTES 73728
#define A_TILE  73728
#define A_SEC   18432
#define SMEM_BYTES (B_BYTES + 2*A_TILE)

__global__ void __launch_bounds__(512) k_all(
    const float* __restrict__ Xm, const float* __restrict__ Xf,
    const float* __restrict__ attrs,
    const float* __restrict__ Wl0, const float* __restrict__ Wl1,
    const float* __restrict__ Wt0, const float* __restrict__ Wt1,
    float* __restrict__ out, int N){
  extern __shared__ char smem[];
  __shared__ int snode[2][128];
  __shared__ int s_grab;
  __shared__ int s_cnt[NAB], s_base[NAB];

  const int tid  = threadIdx.x;
  const int bid  = blockIdx.x;
  const int gthr = bid*NTHR + tid;

  // ===== Phase A: weight prep (grid-strided) =====
  for (int idx = gthr; idx < 20*32768; idx += GRID*NTHR){
    int mat = idx >> 15;
    int r = idx & 32767;
    int k = r >> 7, o = r & 127;
    int type = mat / 10, a = mat - type*10;
    float v;
    if (k < 128) {
      const float* W = type ? Wl1 : Wl0;
      v = W[k*128 + o] * 0.08838834764831845f;
    } else {
      const float* W = type ? Wt1 : Wt0;
      v = W[(k-128)*1280 + a*128 + o] * 0.027950849718747373f;
    }
    int kc = k >> 6, kk = k & 63;
    g_Wh[(size_t)mat*36864 + kc*9216 + o*72 + kk] = __float2half_rn(v);
  }

  // ===== Phase B: hist =====
  if (tid < NAB) s_cnt[tid] = 0;
  __syncthreads();
  for (int n = gthr; n < N; n += GRID*NTHR){
    const float* p = attrs + (size_t)n*NAB;
    int a = 0; float best = p[0];
    #pragma unroll
    for (int i=1;i<NAB;++i){ float v=p[i]; if (v>best){best=v;a=i;} }
    g_zn[n] = a;
    atomicAdd(&s_cnt[a], 1);
  }
  __syncthreads();
  if (tid < NAB) atomicAdd(&g_cnt[tid], s_cnt[tid]);

  gbar(&g_b1);
  if (bid == 0 && tid == 0){
    g_off[0]=0; g_tb_s[0]=0; g_tb_v[0]=0;
    for (int a=0;a<NAB;++a){
      int c = g_cnt[a];
      g_off[a+1]  = g_off[a] + c;
      g_cursor[a] = g_off[a];
      g_tb_s[a+1] = g_tb_s[a] + (c + 127)/128;
      g_tb_v[a+1] = g_tb_v[a] + (c + 41)/42;
    }
    __threadfence();
  }
  gbar(&g_b2);

  // ===== Phase C: scatter =====
  for (int n0 = bid*NTHR; n0 < N; n0 += GRID*NTHR){
    int n = n0 + tid;
    __syncthreads();
    if (tid < NAB) s_cnt[tid] = 0;
    __syncthreads();
    int a = 0, p = 0;
    bool valid = (n < N);
    if (valid){ a = g_zn[n]; p = atomicAdd(&s_cnt[a], 1); }
    __syncthreads();
    if (tid < NAB) s_base[tid] = atomicAdd(&g_cursor[tid], s_cnt[tid]);
    __syncthreads();
    if (valid) g_perm[s_base[a] + p] = n;
  }
  gbar(&g_b3);

  // ===== Phase D: tiled GEMM =====
  const int lane = tid & 31;
  const int wid  = tid >> 5;
  const int wm = wid & 3, wn = wid >> 2;   // 4x4 warps, 32x32 each
  const int g4 = lane >> 2, t4 = lane & 3;
  const unsigned smb = su32(smem);
  const unsigned Ab  = smb + B_BYTES;

  const int ra  = lane & 15;
  const int ca  = (lane >> 4) << 3;
  const int rb  = ((lane >> 4) & 1)*8 + (lane & 7);
  const int cb2 = ((lane >> 3) & 1) << 3;

  VTab vt;
  #pragma unroll
  for (int i=0;i<4;++i){
    int q = tid + i*512;
    if (q < 2016){
      int ln = q/48, u = (q - ln*48) << 2;
      vt.ln[i] = ln; vt.u[i] = u;
      #pragma unroll
      for (int e=0;e<4;++e){
        int jr = u + e;
        int il = jr/3, x = jr - 3*il;
        vt.off[i][e] = (unsigned)((3*ln + x)*144 + il*2);
      }
    } else {
      vt.ln[i] = -1; vt.u[i] = 0;
      #pragma unroll
      for (int e=0;e<4;++e) vt.off[i][e] = 0;
    }
  }

  const int ts_tot = g_tb_s[NAB];
  const int tv_tot = g_tb_v[NAB];
  const int total  = ts_tot + tv_tot;

  if (tid == 0) s_grab = atomicAdd(&g_work, CHUNK);
  __syncthreads();
  int rs = s_grab;
  int re = rs + CHUNK; if (re > total) re = total;
  int t = rs;
  int cur = -1, sp = 0;

  // ---- cold start: gather full A(t) into buffer 0 ----
  if (t < total){
    int isv, base, end, key, width;
    meta(t, ts_tot, isv, base, end, key, width);
    if (tid < width) snode[0][tid] = (base + tid < end) ? g_perm[base + tid] : -1;
    int nd0[4];
    load_nd(isv, base, end, tid, vt, nd0);
    #pragma unroll
    for (int kc = 0; kc < 4; ++kc){
      const float* src = (kc < 2) ? Xm : Xf;
      int cb = isv ? 128 + (kc & 1)*192 : (kc & 1)*64;
      float4 pv[4];
      gath_ld2(src, cb, isv, nd0, tid, vt, pv);
      gath_st2(smem + B_BYTES + kc*A_SEC, isv, tid, vt, pv);
    }
  }

  while (t < total){
    int isv, base, end, key, width;
    meta(t, ts_tot, isv, base, end, key, width);
    if (t == re-1 && tid == 0) s_grab = atomicAdd(&g_work, CHUNK);
    __syncthreads();   // B0: prev tile done; A(t)/snode(t)/s_grab visible

    int nt = (t+1 < re) ? t+1 : s_grab;
    const bool hasN = (nt < total);
    int nisv=0, nbase=0, nend=0, nkey=0, nwidth=0;
    if (hasN) meta(nt, ts_tot, nisv, nbase, nend, nkey, nwidth);

    if (key != cur){
      cur = key;
      const float4* srcW = (const float4*)(g_Wh + (size_t)key*36864);
      float4* dstW = (float4*)smem;
      #pragma unroll 3
      for (int q = tid; q < 4608; q += 512) dstW[q] = srcW[q];
      __syncthreads();  // B0b: B ready (key-change tiles only)
    }

    int nd[4];
    if (hasN){
      load_nd(nisv, nbase, nend, tid, vt, nd);
      if (tid < nwidth) snode[sp^1][tid] = (nbase + tid < nend) ? g_perm[nbase + tid] : -1;
    }

    float acc[2][4][4];
    #pragma unroll
    for (int i=0;i<2;++i)
      #pragma unroll
      for (int j=0;j<4;++j)
        #pragma unroll
        for (int e=0;e<4;++e) acc[i][j][e] = 0.f;

    const unsigned Asp = Ab + (unsigned)(sp*A_TILE);
    char* Adst = smem + B_BYTES + (sp^1)*A_TILE;

    #pragma unroll
    for (int kc = 0; kc < 4; ++kc){
      // prefetch next tile's chunk kc (LDG) — hidden under MMA below
      float4 pv[4];
      if (hasN){
        const float* psrc = (kc < 2) ? Xm : Xf;
        int pcb = nisv ? 128 + (kc & 1)*192 : (kc & 1)*64;
        gath_ld2(psrc, pcb, nisv, nd, tid, vt, pv);
      }
      const unsigned Ac = Asp + (unsigned)(kc*A_SEC);
      const unsigned Bk = smb + (unsigned)(kc*A_SEC);
      #pragma unroll
      for (int ks = 0; ks < 4; ++ks){
        const int k0 = ks*16;
        unsigned af[2][4], bf[2][4];
        ldsm4(af[0], Ac + (unsigned)((wm*32      + ra)*144 + (k0+ca)*2));
        ldsm4(af[1], Ac + (unsigned)((wm*32 + 16 + ra)*144 + (k0+ca)*2));
        ldsm4(bf[0], Bk + (unsigned)((wn*32      + rb)*144 + (k0+cb2)*2));
        ldsm4(bf[1], Bk + (unsigned)((wn*32 + 16 + rb)*144 + (k0+cb2)*2));
        #pragma unroll
        for (int mi = 0; mi < 2; ++mi){
          hmma(acc[mi][0], af[mi], bf[0][0], bf[0][1]);
          hmma(acc[mi][1], af[mi], bf[0][2], bf[0][3]);
          hmma(acc[mi][2], af[mi], bf[1][0], bf[1][1]);
          hmma(acc[mi][3], af[mi], bf[1][2], bf[1][3]);
        }
      }
      if (hasN) gath_st2(Adst + kc*A_SEC, nisv, tid, vt, pv);
    }

    // ---- epilogue ----
    if (!isv){
      #pragma unroll
      for (int mi = 0; mi < 2; ++mi){
        int r0 = wm*32 + mi*16 + g4;
        int n0 = snode[sp][r0], n1 = snode[sp][r0+8];
        #pragma unroll
        for (int jj = 0; jj < 4; ++jj){
          int c = wn*32 + jj*8 + 2*t4;
          if (n0 >= 0)
            *(float2*)(out + (size_t)n0*512 + c) = make_float2(acc[mi][jj][0], acc[mi][jj][1]);
          if (n1 >= 0)
            *(float2*)(out + (size_t)n1*512 + c) = make_float2(acc[mi][jj][2], acc[mi][jj][3]);
        }
      }
    } else {
      __syncthreads();   // B1: all MMA reads of A[sp] done — safe to reuse as stage
      float* stage = (float*)(smem + B_BYTES + sp*A_TILE);
      #pragma unroll
      for (int mi = 0; mi < 2; ++mi){
        int r = wm*32 + mi*16 + g4;
        #pragma unroll
        for (int jj = 0; jj < 4; ++jj){
          int c = wn*32 + jj*8 + 2*t4;
          float* d1 = stage + r*132 + c;
          d1[0] = acc[mi][jj][0]; d1[1] = acc[mi][jj][1];
          float* d2 = stage + (r+8)*132 + c;
          d2[0] = acc[mi][jj][2]; d2[1] = acc[mi][jj][3];
        }
      }
      __syncthreads();   // B2: stage ready
      #pragma unroll
      for (int i = 0; i < 8; ++i){
        int q = tid + i*512;
        if (q >= 4032) break;
        int ln = q / 96, u = (q - ln*96) << 2;
        int node = snode[sp][ln];
        if (node < 0) continue;
        float4 v;
        float* vp = (float*)&v;
        #pragma unroll
        for (int e=0;e<4;++e){
          int jr = u + e;
          int ol = jr/3, x = jr - 3*ol;
          vp[e] = stage[(3*ln + x)*132 + ol];
        }
        *(float4*)(out + (size_t)node*512 + 128 + u) = v;
      }
    }

    sp ^= 1;
    if (t+1 < re){ t = t+1; }
    else { rs = nt; re = rs + CHUNK; if (re > total) re = total; t = nt; }
  }

  // ===== reset globals for deterministic replay =====
  __syncthreads();
  if (tid == 0){
    __threadfence();
    if (atomicAdd(&g_fin, 1) == GRID - 1){
      g_work = 0; g_fin = 0; g_b1 = 0; g_b2 = 0; g_b3 = 0;
      for (int a=0;a<NAB;++a) g_cnt[a] = 0;
      __threadfence();
    }
  }
}

extern "C" void kernel_launch(void* const* d_in, const int* in_sizes, int n_in,
                              void* d_out, int out_size){
  const float* m_i   = (const float*)d_in[0];
  const float* nfeat = (const float*)d_in[1];
  const float* attrs = (const float*)d_in[2];
  const float* Wl0   = (const float*)d_in[3];
  const float* Wl1   = (const float*)d_in[4];
  const float* Wt0   = (const float*)d_in[5];
  const float* Wt1   = (const float*)d_in[6];
  float* out = (float*)d_out;
  int N = in_sizes[0] / 512;
  if (N > MAXN) return;

  cudaFuncSetAttribute(k_all, cudaFuncAttributeMaxDynamicSharedMemorySize, SMEM_BYTES);
  k_all<<<GRID, NTHR, SMEM_BYTES>>>(m_i, nfeat, attrs, Wl0, Wl1, Wt0, Wt1, out, N);
}